// round 1
// baseline (speedup 1.0000x reference)
#include <cuda_runtime.h>
#include <cuda_bf16.h>
#include <cstdint>

// Problem dims
#define BB 8
#define TT 4096
#define DD 1024
#define MM (BB*TT)      // 32768
#define KK DD           // 1024
#define NN DD           // 1024

// GEMM tiling
#define BM 128
#define BN 128
#define BKT 16
#define GEMM_THREADS 256

// Scan chunking
#define NCH 64          // chunks along T
#define LCH 64          // steps per chunk  (64*64 = 4096)
#define NCHAN (BB*DD)   // 8192 channels

// ---------------- device scratch (static: no runtime allocation) ----------------
__device__ float g_delta[(size_t)MM * NN];   // 128 MB
__device__ float g_value[(size_t)MM * NN];   // 128 MB
__device__ float g_Ac[NCH][NCHAN];           // per-chunk product of (1-delta)
__device__ float g_Sc[NCH][NCHAN];           // per-chunk state w/ zero init
__device__ float g_carry[NCH][NCHAN];        // carry-in state for each chunk

// ---------------- f32x2 packed FMA helpers (sm_103a FFMA2 path) ----------------
__device__ __forceinline__ void fma2(unsigned long long& acc,
                                     unsigned long long a2,
                                     unsigned long long b2) {
    asm("fma.rn.f32x2 %0, %1, %2, %0;" : "+l"(acc) : "l"(a2), "l"(b2));
}
__device__ __forceinline__ unsigned long long dup_f32(float a) {
    unsigned long long r;
    asm("mov.b64 %0, {%1, %1};" : "=l"(r) : "f"(a));
    return r;
}
__device__ __forceinline__ void unpack_f32x2(unsigned long long p, float& lo, float& hi) {
    asm("mov.b64 {%0, %1}, %2;" : "=f"(lo), "=f"(hi) : "l"(p));
}

// ---------------- GEMM: C[m,n] = sum_k A[m,k]*W[n,k] + bias[n], optional sigmoid ---
// target: 0 -> g_delta (sigmoid), 1 -> g_value (no sigmoid)
__global__ __launch_bounds__(GEMM_THREADS, 2)
void gemm_bias_kernel(const float* __restrict__ A,
                      const float* __restrict__ W,
                      const float* __restrict__ bias,
                      int target)
{
    __shared__ __align__(16) float As[BKT][BM + 4];   // +4 pad: kill store conflicts
    __shared__ __align__(16) float Bs[BKT][BN + 4];

    float* __restrict__ Cc = (target == 0) ? g_delta : g_value;

    const int tid = threadIdx.x;
    const int m0 = blockIdx.x * BM;
    const int n0 = blockIdx.y * BN;

    // global->shared loader mapping: each thread loads 2 float4 from A and 2 from W
    const int lr = tid >> 2;            // 0..63
    const int lc = (tid & 3) * 4;       // 0,4,8,12
    const float* Aptr = A + (size_t)(m0 + lr) * KK + lc;
    const float* Wptr = W + (size_t)(n0 + lr) * KK + lc;

    // compute mapping: 16x16 threads, 8x8 microtile
    const int tm = tid >> 4;            // 0..15
    const int tn = tid & 15;            // 0..15

    unsigned long long acc[8][4];
    #pragma unroll
    for (int i = 0; i < 8; i++)
        #pragma unroll
        for (int j = 0; j < 4; j++)
            acc[i][j] = 0ULL;           // bits(0,0) == (0.0f, 0.0f)

    for (int kk = 0; kk < KK; kk += BKT) {
        // global loads (issued before the barrier: overlap with prior compute tail)
        float4 a0 = *(const float4*)(Aptr + kk);
        float4 a1 = *(const float4*)(Aptr + kk + (size_t)64 * KK);
        float4 w0 = *(const float4*)(Wptr + kk);
        float4 w1 = *(const float4*)(Wptr + kk + (size_t)64 * KK);

        __syncthreads();
        As[lc + 0][lr] = a0.x; As[lc + 1][lr] = a0.y; As[lc + 2][lr] = a0.z; As[lc + 3][lr] = a0.w;
        As[lc + 0][lr + 64] = a1.x; As[lc + 1][lr + 64] = a1.y; As[lc + 2][lr + 64] = a1.z; As[lc + 3][lr + 64] = a1.w;
        Bs[lc + 0][lr] = w0.x; Bs[lc + 1][lr] = w0.y; Bs[lc + 2][lr] = w0.z; Bs[lc + 3][lr] = w0.w;
        Bs[lc + 0][lr + 64] = w1.x; Bs[lc + 1][lr + 64] = w1.y; Bs[lc + 2][lr + 64] = w1.z; Bs[lc + 3][lr + 64] = w1.w;
        __syncthreads();

        #pragma unroll
        for (int k = 0; k < BKT; k++) {
            float4 mv0 = *(const float4*)&As[k][tm * 8];
            float4 mv1 = *(const float4*)&As[k][tm * 8 + 4];
            const ulonglong2* bp = (const ulonglong2*)&Bs[k][tn * 8];
            ulonglong2 b01 = bp[0];
            ulonglong2 b23 = bp[1];

            float mr[8] = {mv0.x, mv0.y, mv0.z, mv0.w, mv1.x, mv1.y, mv1.z, mv1.w};
            #pragma unroll
            for (int i = 0; i < 8; i++) {
                unsigned long long ad = dup_f32(mr[i]);
                fma2(acc[i][0], ad, b01.x);
                fma2(acc[i][1], ad, b01.y);
                fma2(acc[i][2], ad, b23.x);
                fma2(acc[i][3], ad, b23.y);
            }
        }
    }

    // epilogue: bias (+ sigmoid for delta), vectorized float2 stores
    #pragma unroll
    for (int i = 0; i < 8; i++) {
        const int row = m0 + tm * 8 + i;
        float* outr = Cc + (size_t)row * NN + n0 + tn * 8;
        #pragma unroll
        for (int j = 0; j < 4; j++) {
            float f0, f1;
            unpack_f32x2(acc[i][j], f0, f1);
            f0 += bias[n0 + tn * 8 + j * 2 + 0];
            f1 += bias[n0 + tn * 8 + j * 2 + 1];
            if (target == 0) {
                f0 = 1.0f / (1.0f + __expf(-f0));
                f1 = 1.0f / (1.0f + __expf(-f1));
            }
            *(float2*)(outr + j * 2) = make_float2(f0, f1);
        }
    }
}

// ---------------- scan phase 1: per-(channel,chunk) affine summary -------------
// chunk map: s_out = Aa * s_in + S   with Aa = prod(1-d_t), S = scan from 0
__global__ __launch_bounds__(1024)
void scan_phase1()
{
    const int c = blockIdx.x;     // chunk
    const int b = blockIdx.y;     // batch
    const int d = threadIdx.x;    // feature
    const size_t base = ((size_t)b * TT + (size_t)c * LCH) * DD + d;
    const float* __restrict__ dp = g_delta + base;
    const float* __restrict__ vp = g_value + base;

    float Aa = 1.0f, S = 0.0f;
    #pragma unroll 8
    for (int t = 0; t < LCH; t++) {
        float de = dp[(size_t)t * DD];
        float v  = vp[(size_t)t * DD];
        float a  = 1.0f - de;
        S  = fmaf(a, S, de * v);
        Aa *= a;
    }
    const int ch = b * DD + d;
    g_Ac[c][ch] = Aa;
    g_Sc[c][ch] = S;
}

// ---------------- scan phase 2: carry-in per chunk (tiny) -----------------------
__global__ void scan_phase2()
{
    const int ch = blockIdx.x * blockDim.x + threadIdx.x;
    float cur = 0.0f;
    #pragma unroll
    for (int c = 0; c < NCH; c++) {
        g_carry[c][ch] = cur;
        cur = fmaf(g_Ac[c][ch], cur, g_Sc[c][ch]);
    }
}

// ---------------- scan phase 3: replay with correct carry, emit outputs ---------
__global__ __launch_bounds__(1024)
void scan_phase3(float* __restrict__ out)
{
    const int c = blockIdx.x;
    const int b = blockIdx.y;
    const int d = threadIdx.x;
    const size_t base = ((size_t)b * TT + (size_t)c * LCH) * DD + d;
    const float* __restrict__ dp = g_delta + base;
    const float* __restrict__ vp = g_value + base;
    const int ch = b * DD + d;

    float cur = g_carry[c][ch];
    #pragma unroll 8
    for (int t = 0; t < LCH; t++) {
        float de = dp[(size_t)t * DD];
        float v  = vp[(size_t)t * DD];
        cur = fmaf(1.0f - de, cur, de * v);
        out[base + (size_t)t * DD] = cur;
    }
}

// ---------------- launch -----------------------------------------------------
extern "C" void kernel_launch(void* const* d_in, const int* in_sizes, int n_in,
                              void* d_out, int out_size)
{
    const float* seq = (const float*)d_in[0];
    const float* Wd  = (const float*)d_in[1];
    const float* bd  = (const float*)d_in[2];
    const float* Wv  = (const float*)d_in[3];
    const float* bv  = (const float*)d_in[4];
    float* out = (float*)d_out;

    dim3 ggrid(MM / BM, NN / BN);      // (256, 8)
    gemm_bias_kernel<<<ggrid, GEMM_THREADS>>>(seq, Wd, bd, /*target=*/0); // delta (sigmoid)
    gemm_bias_kernel<<<ggrid, GEMM_THREADS>>>(seq, Wv, bv, /*target=*/1); // value

    scan_phase1<<<dim3(NCH, BB), DD>>>();
    scan_phase2<<<NCHAN / 256, 256>>>();
    scan_phase3<<<dim3(NCH, BB), DD>>>(out);
}

// round 3
// speedup vs baseline: 2.7015x; 2.7015x over previous
#include <cuda_runtime.h>
#include <cuda_bf16.h>
#include <cstdint>

// ---------------- problem dims ----------------
#define BB 8
#define TT 4096
#define DD 1024
#define MM (BB*TT)        // 32768
#define NNall 2048        // concat(delta, value)

// ---------------- GEMM tiling ----------------
#define BM 128
#define BN 128
#define BK 64             // K elems per chunk (64 bf16 = 128B row)
#define NKC 16            // 1024/64
#define MT (MM/BM)        // 256
#define NT (NNall/BN)     // 16

#define S_STAGES 3
#define BUF_A_HI 0
#define BUF_A_LO 16384
#define BUF_B_HI 32768
#define BUF_B_LO 49152
#define STAGE_BYTES 65536
#define SMEM_TOTAL (S_STAGES*STAGE_BYTES)   // 196608

// ---------------- scan chunking ----------------
#define NCH 64
#define LCH 64
#define NCHAN (BB*DD)

// ---------------- device scratch ----------------
__device__ __align__(256) __nv_bfloat16 g_Ahi[(size_t)MM*DD];
__device__ __align__(256) __nv_bfloat16 g_Alo[(size_t)MM*DD];
__device__ __align__(256) __nv_bfloat16 g_Bhi[(size_t)NNall*DD];
__device__ __align__(256) __nv_bfloat16 g_Blo[(size_t)NNall*DD];
__device__ float g_delta[(size_t)MM*DD];
__device__ float g_value[(size_t)MM*DD];
__device__ float g_Ac[NCH][NCHAN];
__device__ float g_Sc[NCH][NCHAN];
__device__ float g_carry[NCH][NCHAN];

// ---------------- PTX helpers (family-independent only) ----------------
__device__ __forceinline__ uint32_t smem_u32(const void* p) {
    uint32_t a;
    asm("{ .reg .u64 t; cvta.to.shared.u64 t, %1; cvt.u32.u64 %0, t; }" : "=r"(a) : "l"(p));
    return a;
}
__device__ __forceinline__ void cp16(uint32_t dst, const void* src) {
    asm volatile("cp.async.cg.shared.global [%0], [%1], 16;" :: "r"(dst), "l"(src) : "memory");
}
__device__ __forceinline__ void cp_commit() {
    asm volatile("cp.async.commit_group;" ::: "memory");
}
template<int N>
__device__ __forceinline__ void cp_wait() {
    asm volatile("cp.async.wait_group %0;" :: "n"(N) : "memory");
}
__device__ __forceinline__ void ldsm4(uint32_t* r, uint32_t addr) {
    asm volatile("ldmatrix.sync.aligned.m8n8.x4.shared.b16 {%0,%1,%2,%3}, [%4];"
        : "=r"(r[0]), "=r"(r[1]), "=r"(r[2]), "=r"(r[3]) : "r"(addr));
}
__device__ __forceinline__ void mma16816(float* c, const uint32_t* a, const uint32_t* b) {
    asm volatile("mma.sync.aligned.m16n8k16.row.col.f32.bf16.bf16.f32 "
        "{%0,%1,%2,%3}, {%4,%5,%6,%7}, {%8,%9}, {%0,%1,%2,%3};"
        : "+f"(c[0]), "+f"(c[1]), "+f"(c[2]), "+f"(c[3])
        : "r"(a[0]), "r"(a[1]), "r"(a[2]), "r"(a[3]), "r"(b[0]), "r"(b[1]));
}

// ---------------- conversion: fp32 -> bf16 hi/lo, plain row-major ----------
__global__ __launch_bounds__(256) void conv_A(const float* __restrict__ seq)
{
    size_t gid = (size_t)blockIdx.x * 256 + threadIdx.x;   // MM*DD/8 = 4,194,304
    size_t e0 = gid * 8;
    float4 x0 = *(const float4*)(seq + e0);
    float4 x1 = *(const float4*)(seq + e0 + 4);
    float xs[8] = {x0.x, x0.y, x0.z, x0.w, x1.x, x1.y, x1.z, x1.w};
    uint32_t hw[8], lw[8];
    #pragma unroll
    for (int i = 0; i < 8; i++) {
        __nv_bfloat16 h = __float2bfloat16_rn(xs[i]);
        __nv_bfloat16 l = __float2bfloat16_rn(xs[i] - __bfloat162float(h));
        hw[i] = (uint32_t)__bfloat16_as_ushort(h);
        lw[i] = (uint32_t)__bfloat16_as_ushort(l);
    }
    *(uint4*)(g_Ahi + e0) = make_uint4(hw[0]|(hw[1]<<16), hw[2]|(hw[3]<<16),
                                       hw[4]|(hw[5]<<16), hw[6]|(hw[7]<<16));
    *(uint4*)(g_Alo + e0) = make_uint4(lw[0]|(lw[1]<<16), lw[2]|(lw[3]<<16),
                                       lw[4]|(lw[5]<<16), lw[6]|(lw[7]<<16));
}

__global__ __launch_bounds__(256) void conv_B(const float* __restrict__ Wd,
                                              const float* __restrict__ Wv)
{
    size_t gid = (size_t)blockIdx.x * 256 + threadIdx.x;   // NNall*DD/8 = 262,144
    size_t e0 = gid * 8;
    int n = (int)(e0 >> 10);
    const float* src = (n < 1024) ? (Wd + e0) : (Wv + e0 - (size_t)1024*1024);
    float4 x0 = *(const float4*)src;
    float4 x1 = *(const float4*)(src + 4);
    float xs[8] = {x0.x, x0.y, x0.z, x0.w, x1.x, x1.y, x1.z, x1.w};
    uint32_t hw[8], lw[8];
    #pragma unroll
    for (int i = 0; i < 8; i++) {
        __nv_bfloat16 h = __float2bfloat16_rn(xs[i]);
        __nv_bfloat16 l = __float2bfloat16_rn(xs[i] - __bfloat162float(h));
        hw[i] = (uint32_t)__bfloat16_as_ushort(h);
        lw[i] = (uint32_t)__bfloat16_as_ushort(l);
    }
    *(uint4*)(g_Bhi + e0) = make_uint4(hw[0]|(hw[1]<<16), hw[2]|(hw[3]<<16),
                                       hw[4]|(hw[5]<<16), hw[6]|(hw[7]<<16));
    *(uint4*)(g_Blo + e0) = make_uint4(lw[0]|(lw[1]<<16), lw[2]|(lw[3]<<16),
                                       lw[4]|(lw[5]<<16), lw[6]|(lw[7]<<16));
}

// ---------------- mma.sync GEMM: D = A * B^T + bias, sigmoid on delta half --
// 3-pass bf16 split: D = Ah*Bh + Ah*Bl + Al*Bh   (ll term ~4e-6, dropped)
__global__ void __launch_bounds__(256, 1)
gemm_mma(const float* __restrict__ bias_d, const float* __restrict__ bias_v)
{
    extern __shared__ __align__(1024) char smem[];
    const uint32_t sb = smem_u32(smem);
    const int tid = threadIdx.x;
    const int nt = blockIdx.x, mt = blockIdx.y;
    const int n0 = nt * BN, m0 = mt * BM;

    const char* gAh = (const char*)(g_Ahi + (size_t)m0 * DD);
    const char* gAl = (const char*)(g_Alo + (size_t)m0 * DD);
    const char* gBh = (const char*)(g_Bhi + (size_t)n0 * DD);
    const char* gBl = (const char*)(g_Blo + (size_t)n0 * DD);

    // ---- loader: 4 x 16B per thread per buffer; SW128 XOR swizzle in smem ----
    // logical (row, unit u of 8) -> phys row*128 + ((u ^ (row&7))<<4)
    auto load_stage = [&](int s, int c) {
        uint32_t st = sb + s * STAGE_BYTES;
        #pragma unroll
        for (int i = 0; i < 4; i++) {
            int uid = i * 256 + tid;           // 0..1023
            int row = uid >> 3, u = uid & 7;
            uint32_t phys = (uint32_t)(row * 128 + (((u ^ (row & 7)) << 4)));
            size_t gofs = (size_t)row * (DD * 2) + (size_t)c * 128 + (size_t)u * 16;
            cp16(st + BUF_A_HI + phys, gAh + gofs);
            cp16(st + BUF_A_LO + phys, gAl + gofs);
            cp16(st + BUF_B_HI + phys, gBh + gofs);
            cp16(st + BUF_B_LO + phys, gBl + gofs);
        }
    };

    // ---- compute mapping: 8 warps in 2(m) x 4(n); warp tile 64x32 ----
    const int lane = tid & 31, wid = tid >> 5;
    const int wm = wid >> 2, wn = wid & 3;

    // ldmatrix lane-address components
    const int arow  = (lane & 7) | (((lane >> 3) & 1) << 3);  // A: rows 0-7,8-15,0-7,8-15
    const int ahalf = lane >> 4;                              // A: k-halves 0,0,1,1
    const int brow  = (lane & 7) | (((lane >> 4) & 1) << 3);  // B: n 0-7,0-7,8-15,8-15
    const int bhalf = (lane >> 3) & 1;                        // B: k-halves 0,1,0,1
    const int sw    = lane & 7;                               // swizzle key (row&7)

    uint32_t aRowOff[4], bRowOff[2];
    #pragma unroll
    for (int mf = 0; mf < 4; mf++) aRowOff[mf] = (uint32_t)((wm * 64 + mf * 16 + arow) * 128);
    #pragma unroll
    for (int np = 0; np < 2; np++) bRowOff[np] = (uint32_t)((wn * 32 + np * 16 + brow) * 128);

    float acc[4][4][4] = {};

    // ---- pipeline prologue ----
    load_stage(0, 0); cp_commit();
    load_stage(1, 1); cp_commit();

    // ---- mainloop ----
    #pragma unroll 1
    for (int c = 0; c < NKC; c++) {
        cp_wait<1>();
        __syncthreads();
        if (c + 2 < NKC) load_stage((c + 2) % S_STAGES, c + 2);
        cp_commit();

        const uint32_t st = sb + (c % S_STAGES) * STAGE_BYTES;
        #pragma unroll
        for (int kk = 0; kk < 4; kk++) {
            const uint32_t aun = (uint32_t)(((kk * 2 + ahalf) ^ sw) << 4);
            const uint32_t bun = (uint32_t)(((kk * 2 + bhalf) ^ sw) << 4);
            uint32_t ah[4][4], al[4][4], bh[4][2], bl[4][2];
            #pragma unroll
            for (int mf = 0; mf < 4; mf++) {
                ldsm4(ah[mf], st + BUF_A_HI + aRowOff[mf] + aun);
                ldsm4(al[mf], st + BUF_A_LO + aRowOff[mf] + aun);
            }
            #pragma unroll
            for (int np = 0; np < 2; np++) {
                uint32_t r[4];
                ldsm4(r, st + BUF_B_HI + bRowOff[np] + bun);
                bh[np*2+0][0] = r[0]; bh[np*2+0][1] = r[1];
                bh[np*2+1][0] = r[2]; bh[np*2+1][1] = r[3];
                ldsm4(r, st + BUF_B_LO + bRowOff[np] + bun);
                bl[np*2+0][0] = r[0]; bl[np*2+0][1] = r[1];
                bl[np*2+1][0] = r[2]; bl[np*2+1][1] = r[3];
            }
            #pragma unroll
            for (int mf = 0; mf < 4; mf++)
                #pragma unroll
                for (int nf = 0; nf < 4; nf++) {
                    mma16816(acc[mf][nf], ah[mf], bh[nf]);
                    mma16816(acc[mf][nf], ah[mf], bl[nf]);
                    mma16816(acc[mf][nf], al[mf], bh[nf]);
                }
        }
    }

    // ---- epilogue: bias (+ sigmoid for delta cols), direct fp32 stores ----
    const bool isd = (n0 < 1024);
    float* __restrict__ outp = isd ? g_delta : g_value;
    const float* __restrict__ bias = isd ? bias_d : bias_v;
    const int ncol = isd ? n0 : (n0 - 1024);
    const int colb = wn * 32 + (lane & 3) * 2;

    float2 bs[4];
    #pragma unroll
    for (int nf = 0; nf < 4; nf++) {
        bs[nf].x = bias[ncol + colb + nf * 8];
        bs[nf].y = bias[ncol + colb + nf * 8 + 1];
    }

    const int r0 = m0 + wm * 64 + (lane >> 2);
    #pragma unroll
    for (int mf = 0; mf < 4; mf++) {
        #pragma unroll
        for (int nf = 0; nf < 4; nf++) {
            const int col = ncol + colb + nf * 8;
            float v0 = acc[mf][nf][0] + bs[nf].x;
            float v1 = acc[mf][nf][1] + bs[nf].y;
            float v2 = acc[mf][nf][2] + bs[nf].x;
            float v3 = acc[mf][nf][3] + bs[nf].y;
            if (isd) {
                v0 = 1.0f / (1.0f + __expf(-v0));
                v1 = 1.0f / (1.0f + __expf(-v1));
                v2 = 1.0f / (1.0f + __expf(-v2));
                v3 = 1.0f / (1.0f + __expf(-v3));
            }
            const int ra = r0 + mf * 16, rb = ra + 8;
            *(float2*)(outp + (size_t)ra * DD + col) = make_float2(v0, v1);
            *(float2*)(outp + (size_t)rb * DD + col) = make_float2(v2, v3);
        }
    }
}

// ---------------- scan (3-phase chunked linear recurrence) ----------------
__global__ __launch_bounds__(1024) void scan_phase1()
{
    const int c = blockIdx.x, b = blockIdx.y, d = threadIdx.x;
    const size_t base = ((size_t)b * TT + (size_t)c * LCH) * DD + d;
    const float* __restrict__ dp = g_delta + base;
    const float* __restrict__ vp = g_value + base;
    float Aa = 1.0f, S = 0.0f;
    #pragma unroll 8
    for (int t = 0; t < LCH; t++) {
        float de = dp[(size_t)t * DD];
        float v  = vp[(size_t)t * DD];
        float a  = 1.0f - de;
        S  = fmaf(a, S, de * v);
        Aa *= a;
    }
    const int ch = b * DD + d;
    g_Ac[c][ch] = Aa;
    g_Sc[c][ch] = S;
}

__global__ void scan_phase2()
{
    const int ch = blockIdx.x * blockDim.x + threadIdx.x;
    float cur = 0.0f;
    #pragma unroll
    for (int c = 0; c < NCH; c++) {
        g_carry[c][ch] = cur;
        cur = fmaf(g_Ac[c][ch], cur, g_Sc[c][ch]);
    }
}

__global__ __launch_bounds__(1024) void scan_phase3(float* __restrict__ out)
{
    const int c = blockIdx.x, b = blockIdx.y, d = threadIdx.x;
    const size_t base = ((size_t)b * TT + (size_t)c * LCH) * DD + d;
    const float* __restrict__ dp = g_delta + base;
    const float* __restrict__ vp = g_value + base;
    const int ch = b * DD + d;
    float cur = g_carry[c][ch];
    #pragma unroll 8
    for (int t = 0; t < LCH; t++) {
        float de = dp[(size_t)t * DD];
        float v  = vp[(size_t)t * DD];
        cur = fmaf(1.0f - de, cur, de * v);
        out[base + (size_t)t * DD] = cur;
    }
}

// ---------------- launch ----------------
extern "C" void kernel_launch(void* const* d_in, const int* in_sizes, int n_in,
                              void* d_out, int out_size)
{
    const float* seq = (const float*)d_in[0];
    const float* Wd  = (const float*)d_in[1];
    const float* bd  = (const float*)d_in[2];
    const float* Wv  = (const float*)d_in[3];
    const float* bv  = (const float*)d_in[4];
    float* out = (float*)d_out;

    cudaFuncSetAttribute(gemm_mma, cudaFuncAttributeMaxDynamicSharedMemorySize, SMEM_TOTAL);

    conv_A<<<16384, 256>>>(seq);
    conv_B<<<1024, 256>>>(Wd, Wv);
    gemm_mma<<<dim3(NT, MT), 256, SMEM_TOTAL>>>(bd, bv);

    scan_phase1<<<dim3(NCH, BB), DD>>>();
    scan_phase2<<<NCHAN / 256, 256>>>();
    scan_phase3<<<dim3(NCH, BB), DD>>>(out);
}

// round 4
// speedup vs baseline: 4.1782x; 1.5466x over previous
#include <cuda_runtime.h>
#include <cuda_fp16.h>
#include <cstdint>

// ---------------- problem dims ----------------
#define BB 8
#define TT 4096
#define DD 1024
#define MM (BB*TT)        // 32768
#define NNall 2048        // concat(delta, value)

// ---------------- GEMM tiling ----------------
#define BM 128
#define BN 128
#define BK 64             // K elems per chunk (64 fp16 = 128B row)
#define NKC 16            // 1024/64
#define MT (MM/BM)        // 256
#define NT (NNall/BN)     // 16

#define S_STAGES 2
#define BUF_A  0
#define BUF_BH 16384
#define BUF_BL 32768
#define STAGE_BYTES 49152
#define SMEM_TOTAL (S_STAGES*STAGE_BYTES)   // 98304 -> 2 CTAs/SM

// ---------------- scan chunking ----------------
#define NCH 64
#define LCH 64
#define NCHAN (BB*DD)

// ---------------- device scratch ----------------
__device__ __align__(256) __half g_A [(size_t)MM*DD];      // 64 MB
__device__ __align__(256) __half g_Bh[(size_t)NNall*DD];   // 4 MB
__device__ __align__(256) __half g_Bl[(size_t)NNall*DD];   // 4 MB
__device__ float g_delta[(size_t)MM*DD];
__device__ float g_value[(size_t)MM*DD];
__device__ float g_Ac[NCH][NCHAN];
__device__ float g_Sc[NCH][NCHAN];
__device__ float g_carry[NCH][NCHAN];

// ---------------- PTX helpers (family-independent only) ----------------
__device__ __forceinline__ uint32_t smem_u32(const void* p) {
    uint32_t a;
    asm("{ .reg .u64 t; cvta.to.shared.u64 t, %1; cvt.u32.u64 %0, t; }" : "=r"(a) : "l"(p));
    return a;
}
__device__ __forceinline__ void cp16(uint32_t dst, const void* src) {
    asm volatile("cp.async.cg.shared.global [%0], [%1], 16;" :: "r"(dst), "l"(src) : "memory");
}
__device__ __forceinline__ void cp_commit() {
    asm volatile("cp.async.commit_group;" ::: "memory");
}
template<int N>
__device__ __forceinline__ void cp_wait() {
    asm volatile("cp.async.wait_group %0;" :: "n"(N) : "memory");
}
__device__ __forceinline__ void ldsm4(uint32_t* r, uint32_t addr) {
    asm volatile("ldmatrix.sync.aligned.m8n8.x4.shared.b16 {%0,%1,%2,%3}, [%4];"
        : "=r"(r[0]), "=r"(r[1]), "=r"(r[2]), "=r"(r[3]) : "r"(addr));
}
__device__ __forceinline__ void mma16816(float* c, const uint32_t* a, const uint32_t* b) {
    asm volatile("mma.sync.aligned.m16n8k16.row.col.f32.f16.f16.f32 "
        "{%0,%1,%2,%3}, {%4,%5,%6,%7}, {%8,%9}, {%0,%1,%2,%3};"
        : "+f"(c[0]), "+f"(c[1]), "+f"(c[2]), "+f"(c[3])
        : "r"(a[0]), "r"(a[1]), "r"(a[2]), "r"(a[3]), "r"(b[0]), "r"(b[1]));
}

// ---------------- conversion ----------------
// A: fp32 -> fp16 (single, rn)
__global__ __launch_bounds__(256) void conv_A(const float* __restrict__ seq)
{
    size_t gid = (size_t)blockIdx.x * 256 + threadIdx.x;   // MM*DD/8 threads
    size_t e0 = gid * 8;
    float4 x0 = *(const float4*)(seq + e0);
    float4 x1 = *(const float4*)(seq + e0 + 4);
    float xs[8] = {x0.x, x0.y, x0.z, x0.w, x1.x, x1.y, x1.z, x1.w};
    uint32_t w[8];
    #pragma unroll
    for (int i = 0; i < 8; i++)
        w[i] = (uint32_t)__half_as_ushort(__float2half_rn(xs[i]));
    *(uint4*)(g_A + e0) = make_uint4(w[0]|(w[1]<<16), w[2]|(w[3]<<16),
                                     w[4]|(w[5]<<16), w[6]|(w[7]<<16));
}

// B: fp32 -> fp16 hi + fp16 lo residual
__global__ __launch_bounds__(256) void conv_B(const float* __restrict__ Wd,
                                              const float* __restrict__ Wv)
{
    size_t gid = (size_t)blockIdx.x * 256 + threadIdx.x;   // NNall*DD/8 threads
    size_t e0 = gid * 8;
    int n = (int)(e0 >> 10);
    const float* src = (n < 1024) ? (Wd + e0) : (Wv + e0 - (size_t)1024*1024);
    float4 x0 = *(const float4*)src;
    float4 x1 = *(const float4*)(src + 4);
    float xs[8] = {x0.x, x0.y, x0.z, x0.w, x1.x, x1.y, x1.z, x1.w};
    uint32_t hw[8], lw[8];
    #pragma unroll
    for (int i = 0; i < 8; i++) {
        __half h = __float2half_rn(xs[i]);
        __half l = __float2half_rn(xs[i] - __half2float(h));
        hw[i] = (uint32_t)__half_as_ushort(h);
        lw[i] = (uint32_t)__half_as_ushort(l);
    }
    *(uint4*)(g_Bh + e0) = make_uint4(hw[0]|(hw[1]<<16), hw[2]|(hw[3]<<16),
                                      hw[4]|(hw[5]<<16), hw[6]|(hw[7]<<16));
    *(uint4*)(g_Bl + e0) = make_uint4(lw[0]|(lw[1]<<16), lw[2]|(lw[3]<<16),
                                      lw[4]|(lw[5]<<16), lw[6]|(lw[7]<<16));
}

// ---------------- mma.sync GEMM: D = A * B^T + bias, sigmoid on delta half --
// fp16 2-pass split: D = A*Bh + A*Bl; dropped (A - fp16(A))*B ~ 2^-12
__global__ void __launch_bounds__(256, 2)
gemm_mma(const float* __restrict__ bias_d, const float* __restrict__ bias_v)
{
    extern __shared__ __align__(1024) char smem[];
    const uint32_t sb = smem_u32(smem);
    const int tid = threadIdx.x;
    const int nt = blockIdx.x, mt = blockIdx.y;
    const int n0 = nt * BN, m0 = mt * BM;

    const char* gA  = (const char*)(g_A  + (size_t)m0 * DD);
    const char* gBh = (const char*)(g_Bh + (size_t)n0 * DD);
    const char* gBl = (const char*)(g_Bl + (size_t)n0 * DD);

    // ---- loader: SW128 XOR swizzle; 4 x 16B per thread per buffer ----
    auto load_stage = [&](int s, int c) {
        uint32_t st = sb + s * STAGE_BYTES;
        #pragma unroll
        for (int i = 0; i < 4; i++) {
            int uid = i * 256 + tid;           // 0..1023
            int row = uid >> 3, u = uid & 7;
            uint32_t phys = (uint32_t)(row * 128 + (((u ^ (row & 7)) << 4)));
            size_t gofs = (size_t)row * (DD * 2) + (size_t)c * 128 + (size_t)u * 16;
            cp16(st + BUF_A  + phys, gA  + gofs);
            cp16(st + BUF_BH + phys, gBh + gofs);
            cp16(st + BUF_BL + phys, gBl + gofs);
        }
    };

    // ---- compute mapping: 8 warps in 2(m) x 4(n); warp tile 64x32 ----
    const int lane = tid & 31, wid = tid >> 5;
    const int wm = wid >> 2, wn = wid & 3;

    const int arow  = lane & 15;                              // A rows 0-15
    const int ahalf = lane >> 4;                              // A k-half
    const int brow  = (lane & 7) | (((lane >> 4) & 1) << 3);  // B n rows
    const int bhalf = (lane >> 3) & 1;                        // B k-half
    const int swA   = arow & 7;
    const int swB   = brow & 7;

    uint32_t aRowOff[4], bRowOff[2];
    #pragma unroll
    for (int mf = 0; mf < 4; mf++) aRowOff[mf] = (uint32_t)((wm * 64 + mf * 16 + arow) * 128);
    #pragma unroll
    for (int np = 0; np < 2; np++) bRowOff[np] = (uint32_t)((wn * 32 + np * 16 + brow) * 128);

    float acc[4][4][4] = {};

    // ---- pipeline prologue (2-stage) ----
    load_stage(0, 0); cp_commit();
    load_stage(1, 1); cp_commit();

    // ---- mainloop ----
    #pragma unroll 1
    for (int c = 0; c < NKC; c++) {
        cp_wait<1>();
        __syncthreads();

        const uint32_t st = sb + (c & 1) * STAGE_BYTES;
        #pragma unroll
        for (int kk = 0; kk < 4; kk++) {
            const uint32_t aun = (uint32_t)(((kk * 2 + ahalf) ^ swA) << 4);
            const uint32_t bun = (uint32_t)(((kk * 2 + bhalf) ^ swB) << 4);
            uint32_t ah[4][4], bh[4][2], bl[4][2];
            #pragma unroll
            for (int mf = 0; mf < 4; mf++)
                ldsm4(ah[mf], st + BUF_A + aRowOff[mf] + aun);
            #pragma unroll
            for (int np = 0; np < 2; np++) {
                uint32_t r[4];
                ldsm4(r, st + BUF_BH + bRowOff[np] + bun);
                bh[np*2+0][0] = r[0]; bh[np*2+0][1] = r[1];
                bh[np*2+1][0] = r[2]; bh[np*2+1][1] = r[3];
                ldsm4(r, st + BUF_BL + bRowOff[np] + bun);
                bl[np*2+0][0] = r[0]; bl[np*2+0][1] = r[1];
                bl[np*2+1][0] = r[2]; bl[np*2+1][1] = r[3];
            }
            #pragma unroll
            for (int mf = 0; mf < 4; mf++)
                #pragma unroll
                for (int nf = 0; nf < 4; nf++) {
                    mma16816(acc[mf][nf], ah[mf], bh[nf]);
                    mma16816(acc[mf][nf], ah[mf], bl[nf]);
                }
        }
        __syncthreads();
        if (c + 2 < NKC) load_stage(c & 1, c + 2);
        cp_commit();
    }

    // ---- epilogue: bias (+ sigmoid for delta cols) ----
    const bool isd = (n0 < 1024);
    float* __restrict__ outp = isd ? g_delta : g_value;
    const float* __restrict__ bias = isd ? bias_d : bias_v;
    const int ncol = isd ? n0 : (n0 - 1024);
    const int colb = wn * 32 + (lane & 3) * 2;

    float2 bs[4];
    #pragma unroll
    for (int nf = 0; nf < 4; nf++) {
        bs[nf].x = bias[ncol + colb + nf * 8];
        bs[nf].y = bias[ncol + colb + nf * 8 + 1];
    }

    const int r0 = m0 + wm * 64 + (lane >> 2);
    #pragma unroll
    for (int mf = 0; mf < 4; mf++) {
        #pragma unroll
        for (int nf = 0; nf < 4; nf++) {
            const int col = ncol + colb + nf * 8;
            float v0 = acc[mf][nf][0] + bs[nf].x;
            float v1 = acc[mf][nf][1] + bs[nf].y;
            float v2 = acc[mf][nf][2] + bs[nf].x;
            float v3 = acc[mf][nf][3] + bs[nf].y;
            if (isd) {
                v0 = 1.0f / (1.0f + __expf(-v0));
                v1 = 1.0f / (1.0f + __expf(-v1));
                v2 = 1.0f / (1.0f + __expf(-v2));
                v3 = 1.0f / (1.0f + __expf(-v3));
            }
            const int ra = r0 + mf * 16, rb = ra + 8;
            *(float2*)(outp + (size_t)ra * DD + col) = make_float2(v0, v1);
            *(float2*)(outp + (size_t)rb * DD + col) = make_float2(v2, v3);
        }
    }
}

// ---------------- scan: 3-phase chunked linear recurrence ----------------
// phase 1: per-(channel,chunk) affine summary; float4 across D
__global__ __launch_bounds__(256) void scan_phase1()
{
    const int c = blockIdx.x, b = blockIdx.y;
    const int d4 = threadIdx.x * 4;
    const size_t base = ((size_t)b * TT + (size_t)c * LCH) * DD + d4;
    float4 Aa = make_float4(1.f, 1.f, 1.f, 1.f);
    float4 S  = make_float4(0.f, 0.f, 0.f, 0.f);
    #pragma unroll 4
    for (int t = 0; t < LCH; t++) {
        float4 de = *(const float4*)(g_delta + base + (size_t)t * DD);
        float4 v  = *(const float4*)(g_value + base + (size_t)t * DD);
        S.x = fmaf(1.f - de.x, S.x, de.x * v.x); Aa.x *= (1.f - de.x);
        S.y = fmaf(1.f - de.y, S.y, de.y * v.y); Aa.y *= (1.f - de.y);
        S.z = fmaf(1.f - de.z, S.z, de.z * v.z); Aa.z *= (1.f - de.z);
        S.w = fmaf(1.f - de.w, S.w, de.w * v.w); Aa.w *= (1.f - de.w);
    }
    const int ch = b * DD + d4;
    *(float4*)&g_Ac[c][ch] = Aa;
    *(float4*)&g_Sc[c][ch] = S;
}

// phase 2: carry-in per chunk; group-prefetched loads (MLP=16)
__global__ __launch_bounds__(256) void scan_phase2()
{
    const int ch = (blockIdx.x * 256 + threadIdx.x) * 4;   // 2048 threads
    float4 cur = make_float4(0.f, 0.f, 0.f, 0.f);
    #pragma unroll 1
    for (int g = 0; g < 8; g++) {
        float4 a[8], s[8];
        #pragma unroll
        for (int j = 0; j < 8; j++) {
            a[j] = *(const float4*)&g_Ac[g * 8 + j][ch];
            s[j] = *(const float4*)&g_Sc[g * 8 + j][ch];
        }
        #pragma unroll
        for (int j = 0; j < 8; j++) {
            *(float4*)&g_carry[g * 8 + j][ch] = cur;
            cur.x = fmaf(a[j].x, cur.x, s[j].x);
            cur.y = fmaf(a[j].y, cur.y, s[j].y);
            cur.z = fmaf(a[j].z, cur.z, s[j].z);
            cur.w = fmaf(a[j].w, cur.w, s[j].w);
        }
    }
}

// phase 3: replay with carry, emit outputs; float4
__global__ __launch_bounds__(256) void scan_phase3(float* __restrict__ out)
{
    const int c = blockIdx.x, b = blockIdx.y;
    const int d4 = threadIdx.x * 4;
    const size_t base = ((size_t)b * TT + (size_t)c * LCH) * DD + d4;
    const int ch = b * DD + d4;
    float4 cur = *(const float4*)&g_carry[c][ch];
    #pragma unroll 4
    for (int t = 0; t < LCH; t++) {
        float4 de = *(const float4*)(g_delta + base + (size_t)t * DD);
        float4 v  = *(const float4*)(g_value + base + (size_t)t * DD);
        cur.x = fmaf(1.f - de.x, cur.x, de.x * v.x);
        cur.y = fmaf(1.f - de.y, cur.y, de.y * v.y);
        cur.z = fmaf(1.f - de.z, cur.z, de.z * v.z);
        cur.w = fmaf(1.f - de.w, cur.w, de.w * v.w);
        *(float4*)(out + base + (size_t)t * DD) = cur;
    }
}

// ---------------- launch ----------------
extern "C" void kernel_launch(void* const* d_in, const int* in_sizes, int n_in,
                              void* d_out, int out_size)
{
    const float* seq = (const float*)d_in[0];
    const float* Wd  = (const float*)d_in[1];
    const float* bd  = (const float*)d_in[2];
    const float* Wv  = (const float*)d_in[3];
    const float* bv  = (const float*)d_in[4];
    float* out = (float*)d_out;

    cudaFuncSetAttribute(gemm_mma, cudaFuncAttributeMaxDynamicSharedMemorySize, SMEM_TOTAL);

    conv_A<<<16384, 256>>>(seq);
    conv_B<<<1024, 256>>>(Wd, Wv);
    gemm_mma<<<dim3(NT, MT), 256, SMEM_TOTAL>>>(bd, bv);

    scan_phase1<<<dim3(NCH, BB), 256>>>();
    scan_phase2<<<8, 256>>>();
    scan_phase3<<<dim3(NCH, BB), 256>>>(out);
}

// round 5
// speedup vs baseline: 6.9994x; 1.6752x over previous
#include <cuda_runtime.h>
#include <cuda_fp16.h>
#include <cstdint>

// ---------------- problem dims ----------------
#define BB 8
#define TT 4096
#define DD 1024
#define MM (BB*TT)        // 32768
#define NNall 2048        // concat(delta, value)

// ---------------- GEMM tiling ----------------
#define BM 128
#define BN 128
#define BK 64             // K elems per chunk (64 fp16 = 128B row)
#define NKC 16            // 1024/64
#define MT (MM/BM)        // 256
#define NT (NNall/BN)     // 16

#define S_STAGES 3
#define BUF_A  0
#define BUF_B  16384
#define STAGE_BYTES 32768
#define SMEM_TOTAL (S_STAGES*STAGE_BYTES)   // 98304 -> 2 CTAs/SM

// ---------------- scan chunking ----------------
#define NCH 64
#define LCH 64
#define NCHAN (BB*DD)

// ---------------- device scratch ----------------
__device__ __align__(256) __half g_A[(size_t)MM*DD];        // 64 MB
__device__ __align__(256) __half g_B[(size_t)NNall*DD];     // 4 MB
__device__ __align__(256) __half g_delta[(size_t)MM*DD];    // 64 MB
__device__ __align__(256) __half g_value[(size_t)MM*DD];    // 64 MB
__device__ float g_Ac[NCH][NCHAN];
__device__ float g_Sc[NCH][NCHAN];
__device__ float g_carry[NCH][NCHAN];

// ---------------- PTX helpers (family-independent only) ----------------
__device__ __forceinline__ uint32_t smem_u32(const void* p) {
    uint32_t a;
    asm("{ .reg .u64 t; cvta.to.shared.u64 t, %1; cvt.u32.u64 %0, t; }" : "=r"(a) : "l"(p));
    return a;
}
__device__ __forceinline__ void cp16(uint32_t dst, const void* src) {
    asm volatile("cp.async.cg.shared.global [%0], [%1], 16;" :: "r"(dst), "l"(src) : "memory");
}
__device__ __forceinline__ void cp_commit() {
    asm volatile("cp.async.commit_group;" ::: "memory");
}
template<int N>
__device__ __forceinline__ void cp_wait() {
    asm volatile("cp.async.wait_group %0;" :: "n"(N) : "memory");
}
__device__ __forceinline__ void ldsm4(uint32_t* r, uint32_t addr) {
    asm volatile("ldmatrix.sync.aligned.m8n8.x4.shared.b16 {%0,%1,%2,%3}, [%4];"
        : "=r"(r[0]), "=r"(r[1]), "=r"(r[2]), "=r"(r[3]) : "r"(addr));
}
__device__ __forceinline__ void mma16816(float* c, const uint32_t* a, const uint32_t* b) {
    asm volatile("mma.sync.aligned.m16n8k16.row.col.f32.f16.f16.f32 "
        "{%0,%1,%2,%3}, {%4,%5,%6,%7}, {%8,%9}, {%0,%1,%2,%3};"
        : "+f"(c[0]), "+f"(c[1]), "+f"(c[2]), "+f"(c[3])
        : "r"(a[0]), "r"(a[1]), "r"(a[2]), "r"(a[3]), "r"(b[0]), "r"(b[1]));
}

// ---------------- conversion ----------------
__global__ __launch_bounds__(256) void conv_A(const float* __restrict__ seq)
{
    size_t gid = (size_t)blockIdx.x * 256 + threadIdx.x;   // MM*DD/8 threads
    size_t e0 = gid * 8;
    float4 x0 = *(const float4*)(seq + e0);
    float4 x1 = *(const float4*)(seq + e0 + 4);
    float xs[8] = {x0.x, x0.y, x0.z, x0.w, x1.x, x1.y, x1.z, x1.w};
    uint32_t w[8];
    #pragma unroll
    for (int i = 0; i < 8; i++)
        w[i] = (uint32_t)__half_as_ushort(__float2half_rn(xs[i]));
    *(uint4*)(g_A + e0) = make_uint4(w[0]|(w[1]<<16), w[2]|(w[3]<<16),
                                     w[4]|(w[5]<<16), w[6]|(w[7]<<16));
}

__global__ __launch_bounds__(256) void conv_B(const float* __restrict__ Wd,
                                              const float* __restrict__ Wv)
{
    size_t gid = (size_t)blockIdx.x * 256 + threadIdx.x;   // NNall*DD/8 threads
    size_t e0 = gid * 8;
    int n = (int)(e0 >> 10);
    const float* src = (n < 1024) ? (Wd + e0) : (Wv + e0 - (size_t)1024*1024);
    float4 x0 = *(const float4*)src;
    float4 x1 = *(const float4*)(src + 4);
    float xs[8] = {x0.x, x0.y, x0.z, x0.w, x1.x, x1.y, x1.z, x1.w};
    uint32_t w[8];
    #pragma unroll
    for (int i = 0; i < 8; i++)
        w[i] = (uint32_t)__half_as_ushort(__float2half_rn(xs[i]));
    *(uint4*)(g_B + e0) = make_uint4(w[0]|(w[1]<<16), w[2]|(w[3]<<16),
                                     w[4]|(w[5]<<16), w[6]|(w[7]<<16));
}

// ---------------- mma.sync GEMM: D = A * B^T + bias, sigmoid on delta half --
// single-pass fp16 (rel_err budget ~3.5e-4 << 1e-3)
__global__ void __launch_bounds__(256, 2)
gemm_mma(const float* __restrict__ bias_d, const float* __restrict__ bias_v)
{
    extern __shared__ __align__(1024) char smem[];
    const uint32_t sb = smem_u32(smem);
    const int tid = threadIdx.x;
    const int nt = blockIdx.x, mt = blockIdx.y;
    const int n0 = nt * BN, m0 = mt * BM;

    const char* gA = (const char*)(g_A + (size_t)m0 * DD);
    const char* gB = (const char*)(g_B + (size_t)n0 * DD);

    // ---- loader: SW128 XOR swizzle; 4 x 16B per thread per buffer ----
    auto load_stage = [&](int s, int c) {
        uint32_t st = sb + s * STAGE_BYTES;
        #pragma unroll
        for (int i = 0; i < 4; i++) {
            int uid = i * 256 + tid;           // 0..1023
            int row = uid >> 3, u = uid & 7;
            uint32_t phys = (uint32_t)(row * 128 + (((u ^ (row & 7)) << 4)));
            size_t gofs = (size_t)row * (DD * 2) + (size_t)c * 128 + (size_t)u * 16;
            cp16(st + BUF_A + phys, gA + gofs);
            cp16(st + BUF_B + phys, gB + gofs);
        }
    };

    // ---- compute mapping: 8 warps in 2(m) x 4(n); warp tile 64x32 ----
    const int lane = tid & 31, wid = tid >> 5;
    const int wm = wid >> 2, wn = wid & 3;

    const int arow  = lane & 15;                              // A rows 0-15
    const int ahalf = lane >> 4;                              // A k-half
    const int brow  = (lane & 7) | (((lane >> 4) & 1) << 3);  // B n rows
    const int bhalf = (lane >> 3) & 1;                        // B k-half
    const int swA   = arow & 7;
    const int swB   = brow & 7;

    uint32_t aRowOff[4], bRowOff[2];
    #pragma unroll
    for (int mf = 0; mf < 4; mf++) aRowOff[mf] = (uint32_t)((wm * 64 + mf * 16 + arow) * 128);
    #pragma unroll
    for (int np = 0; np < 2; np++) bRowOff[np] = (uint32_t)((wn * 32 + np * 16 + brow) * 128);

    float acc[4][4][4] = {};

    // ---- pipeline prologue (3-stage) ----
    load_stage(0, 0); cp_commit();
    load_stage(1, 1); cp_commit();
    load_stage(2, 2); cp_commit();

    // ---- mainloop ----
    #pragma unroll 1
    for (int c = 0; c < NKC; c++) {
        cp_wait<2>();
        __syncthreads();

        const int s = c % S_STAGES;
        const uint32_t st = sb + s * STAGE_BYTES;
        #pragma unroll
        for (int kk = 0; kk < 4; kk++) {
            const uint32_t aun = (uint32_t)(((kk * 2 + ahalf) ^ swA) << 4);
            const uint32_t bun = (uint32_t)(((kk * 2 + bhalf) ^ swB) << 4);
            uint32_t ah[4][4], bh[4][2];
            #pragma unroll
            for (int mf = 0; mf < 4; mf++)
                ldsm4(ah[mf], st + BUF_A + aRowOff[mf] + aun);
            #pragma unroll
            for (int np = 0; np < 2; np++) {
                uint32_t r[4];
                ldsm4(r, st + BUF_B + bRowOff[np] + bun);
                bh[np*2+0][0] = r[0]; bh[np*2+0][1] = r[1];
                bh[np*2+1][0] = r[2]; bh[np*2+1][1] = r[3];
            }
            #pragma unroll
            for (int mf = 0; mf < 4; mf++)
                #pragma unroll
                for (int nf = 0; nf < 4; nf++)
                    mma16816(acc[mf][nf], ah[mf], bh[nf]);
        }
        __syncthreads();
        if (c + 3 < NKC) { load_stage(s, c + 3); }
        cp_commit();
    }

    // ---- epilogue: bias (+ sigmoid for delta cols), fp16 stores ----
    const bool isd = (n0 < 1024);
    __half* __restrict__ outp = isd ? g_delta : g_value;
    const float* __restrict__ bias = isd ? bias_d : bias_v;
    const int ncol = isd ? n0 : (n0 - 1024);
    const int colb = wn * 32 + (lane & 3) * 2;

    float2 bs[4];
    #pragma unroll
    for (int nf = 0; nf < 4; nf++) {
        bs[nf].x = bias[ncol + colb + nf * 8];
        bs[nf].y = bias[ncol + colb + nf * 8 + 1];
    }

    const int r0 = m0 + wm * 64 + (lane >> 2);
    #pragma unroll
    for (int mf = 0; mf < 4; mf++) {
        #pragma unroll
        for (int nf = 0; nf < 4; nf++) {
            const int col = ncol + colb + nf * 8;
            float v0 = acc[mf][nf][0] + bs[nf].x;
            float v1 = acc[mf][nf][1] + bs[nf].y;
            float v2 = acc[mf][nf][2] + bs[nf].x;
            float v3 = acc[mf][nf][3] + bs[nf].y;
            if (isd) {
                v0 = 1.0f / (1.0f + __expf(-v0));
                v1 = 1.0f / (1.0f + __expf(-v1));
                v2 = 1.0f / (1.0f + __expf(-v2));
                v3 = 1.0f / (1.0f + __expf(-v3));
            }
            const int ra = r0 + mf * 16, rb = ra + 8;
            *(__half2*)(outp + (size_t)ra * DD + col) = __floats2half2_rn(v0, v1);
            *(__half2*)(outp + (size_t)rb * DD + col) = __floats2half2_rn(v2, v3);
        }
    }
}

// ---------------- scan: 3-phase chunked linear recurrence (fp16 inputs) -----
__device__ __forceinline__ float4 ld_h4(const __half* p) {
    uint2 u = *(const uint2*)p;
    float2 a = __half22float2(*(__half2*)&u.x);
    float2 b = __half22float2(*(__half2*)&u.y);
    return make_float4(a.x, a.y, b.x, b.y);
}

__global__ __launch_bounds__(256) void scan_phase1()
{
    const int c = blockIdx.x, b = blockIdx.y;
    const int d4 = threadIdx.x * 4;
    const size_t base = ((size_t)b * TT + (size_t)c * LCH) * DD + d4;
    float4 Aa = make_float4(1.f, 1.f, 1.f, 1.f);
    float4 S  = make_float4(0.f, 0.f, 0.f, 0.f);
    #pragma unroll 4
    for (int t = 0; t < LCH; t++) {
        float4 de = ld_h4(g_delta + base + (size_t)t * DD);
        float4 v  = ld_h4(g_value + base + (size_t)t * DD);
        S.x = fmaf(1.f - de.x, S.x, de.x * v.x); Aa.x *= (1.f - de.x);
        S.y = fmaf(1.f - de.y, S.y, de.y * v.y); Aa.y *= (1.f - de.y);
        S.z = fmaf(1.f - de.z, S.z, de.z * v.z); Aa.z *= (1.f - de.z);
        S.w = fmaf(1.f - de.w, S.w, de.w * v.w); Aa.w *= (1.f - de.w);
    }
    const int ch = b * DD + d4;
    *(float4*)&g_Ac[c][ch] = Aa;
    *(float4*)&g_Sc[c][ch] = S;
}

__global__ __launch_bounds__(256) void scan_phase2()
{
    const int ch = (blockIdx.x * 256 + threadIdx.x) * 4;   // 2048 threads
    float4 cur = make_float4(0.f, 0.f, 0.f, 0.f);
    #pragma unroll 1
    for (int g = 0; g < 8; g++) {
        float4 a[8], s[8];
        #pragma unroll
        for (int j = 0; j < 8; j++) {
            a[j] = *(const float4*)&g_Ac[g * 8 + j][ch];
            s[j] = *(const float4*)&g_Sc[g * 8 + j][ch];
        }
        #pragma unroll
        for (int j = 0; j < 8; j++) {
            *(float4*)&g_carry[g * 8 + j][ch] = cur;
            cur.x = fmaf(a[j].x, cur.x, s[j].x);
            cur.y = fmaf(a[j].y, cur.y, s[j].y);
            cur.z = fmaf(a[j].z, cur.z, s[j].z);
            cur.w = fmaf(a[j].w, cur.w, s[j].w);
        }
    }
}

__global__ __launch_bounds__(256) void scan_phase3(float* __restrict__ out)
{
    const int c = blockIdx.x, b = blockIdx.y;
    const int d4 = threadIdx.x * 4;
    const size_t base = ((size_t)b * TT + (size_t)c * LCH) * DD + d4;
    const int ch = b * DD + d4;
    float4 cur = *(const float4*)&g_carry[c][ch];
    #pragma unroll 4
    for (int t = 0; t < LCH; t++) {
        float4 de = ld_h4(g_delta + base + (size_t)t * DD);
        float4 v  = ld_h4(g_value + base + (size_t)t * DD);
        cur.x = fmaf(1.f - de.x, cur.x, de.x * v.x);
        cur.y = fmaf(1.f - de.y, cur.y, de.y * v.y);
        cur.z = fmaf(1.f - de.z, cur.z, de.z * v.z);
        cur.w = fmaf(1.f - de.w, cur.w, de.w * v.w);
        *(float4*)(out + base + (size_t)t * DD) = cur;
    }
}

// ---------------- launch ----------------
extern "C" void kernel_launch(void* const* d_in, const int* in_sizes, int n_in,
                              void* d_out, int out_size)
{
    const float* seq = (const float*)d_in[0];
    const float* Wd  = (const float*)d_in[1];
    const float* bd  = (const float*)d_in[2];
    const float* Wv  = (const float*)d_in[3];
    const float* bv  = (const float*)d_in[4];
    float* out = (float*)d_out;

    cudaFuncSetAttribute(gemm_mma, cudaFuncAttributeMaxDynamicSharedMemorySize, SMEM_TOTAL);

    conv_A<<<16384, 256>>>(seq);
    conv_B<<<1024, 256>>>(Wd, Wv);
    gemm_mma<<<dim3(NT, MT), 256, SMEM_TOTAL>>>(bd, bv);

    scan_phase1<<<dim3(NCH, BB), 256>>>();
    scan_phase2<<<8, 256>>>();
    scan_phase3<<<dim3(NCH, BB), 256>>>(out);
}

// round 6
// speedup vs baseline: 7.1378x; 1.0198x over previous
#include <cuda_runtime.h>
#include <cuda_fp16.h>
#include <cstdint>

// ---------------- problem dims ----------------
#define BB 8
#define TT 4096
#define DD 1024
#define MM (BB*TT)        // 32768
#define NBR 2048          // interleaved B rows: row = 2*d + s (s=0 delta, 1 value)

// ---------------- GEMM tiling ----------------
#define BM 128
#define BN 128            // B rows per CTA = 64 d's (delta+value interleaved)
#define NKC 16            // 1024/64 K-chunks
#define MT (MM/BM)        // 256
#define NT (NBR/BN)       // 16

#define S_STAGES 3
#define BUF_A  0
#define BUF_B  16384
#define STAGE_BYTES 32768
#define SMEM_TOTAL (S_STAGES*STAGE_BYTES)   // 98304 -> 2 CTAs/SM

// ---------------- scan chunking: chunk == M-tile (128 t) ----------------
#define NCHB 32           // chunks per batch
#define NCHT 256          // total chunks (== MT)

// ---------------- device scratch ----------------
__device__ __align__(256) __half   g_A[(size_t)MM*DD];      // 64 MB fp16 A
__device__ __align__(256) __half   g_B[(size_t)NBR*DD];     // 4 MB interleaved W
__device__ __align__(256) uint32_t g_ab[(size_t)MM*DD];     // 128 MB half2(a,b) per (t,d)
__device__ float2 g_AS[NCHT][DD];                           // chunk affine (A,S)
__device__ float  g_carry[NCHT][DD];                        // chunk carry-in state

// ---------------- PTX helpers (family-independent only) ----------------
__device__ __forceinline__ uint32_t smem_u32(const void* p) {
    uint32_t a;
    asm("{ .reg .u64 t; cvta.to.shared.u64 t, %1; cvt.u32.u64 %0, t; }" : "=r"(a) : "l"(p));
    return a;
}
__device__ __forceinline__ void cp16(uint32_t dst, const void* src) {
    asm volatile("cp.async.cg.shared.global [%0], [%1], 16;" :: "r"(dst), "l"(src) : "memory");
}
__device__ __forceinline__ void cp_commit() {
    asm volatile("cp.async.commit_group;" ::: "memory");
}
template<int N>
__device__ __forceinline__ void cp_wait() {
    asm volatile("cp.async.wait_group %0;" :: "n"(N) : "memory");
}
__device__ __forceinline__ void ldsm4(uint32_t* r, uint32_t addr) {
    asm volatile("ldmatrix.sync.aligned.m8n8.x4.shared.b16 {%0,%1,%2,%3}, [%4];"
        : "=r"(r[0]), "=r"(r[1]), "=r"(r[2]), "=r"(r[3]) : "r"(addr));
}
__device__ __forceinline__ void mma16816(float* c, const uint32_t* a, const uint32_t* b) {
    asm volatile("mma.sync.aligned.m16n8k16.row.col.f32.f16.f16.f32 "
        "{%0,%1,%2,%3}, {%4,%5,%6,%7}, {%8,%9}, {%0,%1,%2,%3};"
        : "+f"(c[0]), "+f"(c[1]), "+f"(c[2]), "+f"(c[3])
        : "r"(a[0]), "r"(a[1]), "r"(a[2]), "r"(a[3]), "r"(b[0]), "r"(b[1]));
}
__device__ __forceinline__ float fast_sigmoid(float x) {
    float t;
    asm("tanh.approx.f32 %0, %1;" : "=f"(t) : "f"(x * 0.5f));
    return fmaf(t, 0.5f, 0.5f);
}

// ---------------- conversion ----------------
__global__ __launch_bounds__(256) void conv_A(const float* __restrict__ seq)
{
    size_t gid = (size_t)blockIdx.x * 256 + threadIdx.x;   // MM*DD/8 threads
    size_t e0 = gid * 8;
    float4 x0 = *(const float4*)(seq + e0);
    float4 x1 = *(const float4*)(seq + e0 + 4);
    float xs[8] = {x0.x, x0.y, x0.z, x0.w, x1.x, x1.y, x1.z, x1.w};
    uint32_t w[8];
    #pragma unroll
    for (int i = 0; i < 8; i++)
        w[i] = (uint32_t)__half_as_ushort(__float2half_rn(xs[i]));
    *(uint4*)(g_A + e0) = make_uint4(w[0]|(w[1]<<16), w[2]|(w[3]<<16),
                                     w[4]|(w[5]<<16), w[6]|(w[7]<<16));
}

// B: interleave rows — g_B row r = 2*d+s <- (s ? Wv : Wd)[d]
__global__ __launch_bounds__(256) void conv_B(const float* __restrict__ Wd,
                                              const float* __restrict__ Wv)
{
    size_t gid = (size_t)blockIdx.x * 256 + threadIdx.x;   // NBR*DD/8 = 262144
    int r  = (int)(gid >> 7);        // 0..2047
    int k0 = ((int)gid & 127) * 8;
    int d  = r >> 1, s = r & 1;
    const float* src = (s ? Wv : Wd) + (size_t)d * DD + k0;
    float4 x0 = *(const float4*)src;
    float4 x1 = *(const float4*)(src + 4);
    float xs[8] = {x0.x, x0.y, x0.z, x0.w, x1.x, x1.y, x1.z, x1.w};
    uint32_t w[8];
    #pragma unroll
    for (int i = 0; i < 8; i++)
        w[i] = (uint32_t)__half_as_ushort(__float2half_rn(xs[i]));
    *(uint4*)(g_B + (size_t)r * DD + k0) =
        make_uint4(w[0]|(w[1]<<16), w[2]|(w[3]<<16), w[4]|(w[5]<<16), w[6]|(w[7]<<16));
}

// ---------------- GEMM + fused gate epilogue + chunk summary ----------------
__global__ void __launch_bounds__(256, 2)
gemm_mma(const float* __restrict__ bias_d, const float* __restrict__ bias_v)
{
    extern __shared__ __align__(1024) char smem[];
    const uint32_t sb = smem_u32(smem);
    const int tid = threadIdx.x;
    const int nt = blockIdx.x, mt = blockIdx.y;
    const int m0 = mt * BM;

    const char* gA = (const char*)(g_A + (size_t)m0 * DD);
    const char* gB = (const char*)(g_B + (size_t)nt * BN * DD);

    // ---- loader: SW128 XOR swizzle; 4 x 16B per thread per buffer ----
    auto load_stage = [&](int s, int c) {
        uint32_t st = sb + s * STAGE_BYTES;
        #pragma unroll
        for (int i = 0; i < 4; i++) {
            int uid = i * 256 + tid;           // 0..1023
            int row = uid >> 3, u = uid & 7;
            uint32_t phys = (uint32_t)(row * 128 + (((u ^ (row & 7)) << 4)));
            size_t gofs = (size_t)row * (DD * 2) + (size_t)c * 128 + (size_t)u * 16;
            cp16(st + BUF_A + phys, gA + gofs);
            cp16(st + BUF_B + phys, gB + gofs);
        }
    };

    // ---- compute mapping: 8 warps in 2(m) x 4(n); warp tile 64x32 ----
    const int lane = tid & 31, wid = tid >> 5;
    const int wm = wid >> 2, wn = wid & 3;

    const int arow  = lane & 15;
    const int ahalf = lane >> 4;
    const int brow  = (lane & 7) | (((lane >> 4) & 1) << 3);
    const int bhalf = (lane >> 3) & 1;
    const int swA   = arow & 7;
    const int swB   = brow & 7;

    uint32_t aRowOff[4], bRowOff[2];
    #pragma unroll
    for (int mf = 0; mf < 4; mf++) aRowOff[mf] = (uint32_t)((wm * 64 + mf * 16 + arow) * 128);
    #pragma unroll
    for (int np = 0; np < 2; np++) bRowOff[np] = (uint32_t)((wn * 32 + np * 16 + brow) * 128);

    float acc[4][4][4] = {};

    load_stage(0, 0); cp_commit();
    load_stage(1, 1); cp_commit();
    load_stage(2, 2); cp_commit();

    #pragma unroll 1
    for (int c = 0; c < NKC; c++) {
        cp_wait<2>();
        __syncthreads();

        const int s = c % S_STAGES;
        const uint32_t st = sb + s * STAGE_BYTES;
        #pragma unroll
        for (int kk = 0; kk < 4; kk++) {
            const uint32_t aun = (uint32_t)(((kk * 2 + ahalf) ^ swA) << 4);
            const uint32_t bun = (uint32_t)(((kk * 2 + bhalf) ^ swB) << 4);
            uint32_t ah[4][4], bh[4][2];
            #pragma unroll
            for (int mf = 0; mf < 4; mf++)
                ldsm4(ah[mf], st + BUF_A + aRowOff[mf] + aun);
            #pragma unroll
            for (int np = 0; np < 2; np++) {
                uint32_t r[4];
                ldsm4(r, st + BUF_B + bRowOff[np] + bun);
                bh[np*2+0][0] = r[0]; bh[np*2+0][1] = r[1];
                bh[np*2+1][0] = r[2]; bh[np*2+1][1] = r[3];
            }
            #pragma unroll
            for (int mf = 0; mf < 4; mf++)
                #pragma unroll
                for (int nf = 0; nf < 4; nf++)
                    mma16816(acc[mf][nf], ah[mf], bh[nf]);
        }
        __syncthreads();
        if (c + 3 < NKC) { load_stage(s, c + 3); }
        cp_commit();
    }

    // ==== fused epilogue ====
    // acc[mf][nf][0,1] = (delta_hat, value_hat) at row ra, d;  [2,3] same at ra+8
    // d(global) = nt*64 + wn*16 + nf*4 + (lane&3)
    // t(local in chunk) = wm*64 + mf*16 + p*8 + (lane>>2)
    const int dbase = nt * 64 + wn * 16 + (lane & 3);
    const int j = lane >> 2;                 // t-bit [0,8) across lanes

    float2* sEp = (float2*)smem;             // 128 float2 staging (reuse stages)
    __syncthreads();                         // everyone done with smem tiles

    #pragma unroll
    for (int nf = 0; nf < 4; nf++) {
        const int dg = dbase + nf * 4;
        const float bd = bias_d[dg];
        const float bv = bias_v[dg];

        float Ca = 1.0f, Cb = 0.0f;          // running warp-block composition
        #pragma unroll
        for (int mf = 0; mf < 4; mf++) {
            #pragma unroll
            for (int p = 0; p < 2; p++) {    // g = mf*2+p ascending == t ascending
                float dh = acc[mf][nf][p*2+0] + bd;
                float vh = acc[mf][nf][p*2+1] + bv;
                float del = fast_sigmoid(dh);
                float a = 1.0f - del;
                float b = del * vh;
                // store half2(a,b)
                const int row = m0 + wm * 64 + mf * 16 + p * 8 + j;
                __half2 h = __floats2half2_rn(a, b);
                g_ab[(size_t)row * DD + dg] = *(uint32_t*)&h;
                // ordered butterfly over j (lane bits 2..4): segment product of 8 t's
                float Wa = a, Wb = b;
                #pragma unroll
                for (int mk = 4; mk <= 16; mk <<= 1) {
                    float oa = __shfl_xor_sync(0xffffffffu, Wa, mk);
                    float ob = __shfl_xor_sync(0xffffffffu, Wb, mk);
                    if (lane & mk) {         // self upper: self ∘ other
                        Wb = fmaf(Wa, ob, Wb);
                        Wa = Wa * oa;
                    } else {                 // other upper: other ∘ self
                        Wb = fmaf(oa, Wb, ob);
                        Wa = oa * Wa;
                    }
                }
                // compose into running chunk map: C = W ∘ C
                Cb = fmaf(Wa, Cb, Wb);
                Ca = Wa * Ca;
            }
        }
        if (j == 0)                          // one lane per d per warp-block
            sEp[wm * 64 + wn * 16 + nf * 4 + (lane & 3)] = make_float2(Ca, Cb);
    }
    __syncthreads();
    if (tid < 64) {                          // compose wm=1 ∘ wm=0, publish chunk map
        float2 lo = sEp[tid], hi = sEp[64 + tid];
        g_AS[mt][nt * 64 + tid] = make_float2(hi.x * lo.x, fmaf(hi.x, lo.y, hi.y));
    }
}

// ---------------- scan phase 2: carry-in per chunk (tiny) ----------------
__global__ __launch_bounds__(256) void scan_phase2()
{
    const int g = blockIdx.x * 256 + threadIdx.x;   // 2048 threads
    const int b = g >> 8;
    const int d0 = (g & 255) * 4;
    float4 cur = make_float4(0.f, 0.f, 0.f, 0.f);
    #pragma unroll 4
    for (int c = 0; c < NCHB; c++) {
        const int mt = b * NCHB + c;
        const float4* asp = (const float4*)&g_AS[mt][d0];
        float4 x = asp[0];   // (a0,s0,a1,s1)
        float4 y = asp[1];   // (a2,s2,a3,s3)
        *(float4*)&g_carry[mt][d0] = cur;
        cur.x = fmaf(x.x, cur.x, x.y);
        cur.y = fmaf(x.z, cur.y, x.w);
        cur.z = fmaf(y.x, cur.z, y.y);
        cur.w = fmaf(y.z, cur.w, y.w);
    }
}

// ---------------- scan phase 3: replay chunk with carry, emit fp32 ----------
__global__ __launch_bounds__(256) void scan_phase3(float* __restrict__ out)
{
    const int c = blockIdx.x, b = blockIdx.y;
    const int mt = b * NCHB + c;
    const int d4 = threadIdx.x * 4;
    const size_t base = (size_t)mt * BM * DD + d4;   // row mt*128, col d4
    float4 cur = *(const float4*)&g_carry[mt][d4];
    #pragma unroll 4
    for (int tl = 0; tl < BM; tl++) {
        uint4 u = *(const uint4*)(g_ab + base + (size_t)tl * DD);
        float2 p0 = __half22float2(*(__half2*)&u.x);
        float2 p1 = __half22float2(*(__half2*)&u.y);
        float2 p2 = __half22float2(*(__half2*)&u.z);
        float2 p3 = __half22float2(*(__half2*)&u.w);
        cur.x = fmaf(p0.x, cur.x, p0.y);
        cur.y = fmaf(p1.x, cur.y, p1.y);
        cur.z = fmaf(p2.x, cur.z, p2.y);
        cur.w = fmaf(p3.x, cur.w, p3.y);
        *(float4*)(out + base + (size_t)tl * DD) = cur;
    }
}

// ---------------- launch ----------------
extern "C" void kernel_launch(void* const* d_in, const int* in_sizes, int n_in,
                              void* d_out, int out_size)
{
    const float* seq = (const float*)d_in[0];
    const float* Wd  = (const float*)d_in[1];
    const float* bd  = (const float*)d_in[2];
    const float* Wv  = (const float*)d_in[3];
    const float* bv  = (const float*)d_in[4];
    float* out = (float*)d_out;

    cudaFuncSetAttribute(gemm_mma, cudaFuncAttributeMaxDynamicSharedMemorySize, SMEM_TOTAL);

    conv_A<<<16384, 256>>>(seq);
    conv_B<<<1024, 256>>>(Wd, Wv);
    gemm_mma<<<dim3(NT, MT), 256, SMEM_TOTAL>>>(bd, bv);

    scan_phase2<<<8, 256>>>();
    scan_phase3<<<dim3(NCHB, BB), 256>>>(out);
}

// round 7
// speedup vs baseline: 7.4934x; 1.0498x over previous
#include <cuda_runtime.h>
#include <cuda_fp16.h>
#include <cstdint>

// ---------------- problem dims ----------------
#define BB 8
#define TT 4096
#define DD 1024
#define MM (BB*TT)        // 32768
#define NBR 2048          // interleaved B rows: row = 2*d + s (s=0 delta, 1 value)

// ---------------- GEMM tiling ----------------
#define BM 128
#define BN 128            // 64 d's (delta+value interleaved)
#define NKC 16            // 1024/64 K-chunks
#define MT (MM/BM)        // 256
#define NT (NBR/BN)       // 16

#define S_STAGES 3
#define BUF_A  0
#define BUF_B  16384
#define STAGE_BYTES 32768
#define SMEM_TOTAL (S_STAGES*STAGE_BYTES)   // 98304 -> 2 CTAs/SM

// ---------------- scan chunking: chunk == 64 t (wm granularity) ----------------
#define NCHB 64           // chunks per batch
#define NCHT 512          // total chunks (== MT*2)

// ---------------- device scratch ----------------
__device__ __align__(256) __half   g_A[(size_t)MM*DD];      // 64 MB fp16 A
__device__ __align__(256) __half   g_B[(size_t)NBR*DD];     // 4 MB interleaved W
// g_ab in warp-native layout (u32 = half2(a,b)):
// idx = (((((mt*16+nt)*2+wm)*4+wn)*4+nf)*4+mf)*2+p)*32 + lane
__device__ __align__(256) uint32_t g_ab[(size_t)MM*DD];     // 128 MB
__device__ float2 g_AS[NCHT][DD];                           // chunk affine (A,S)
__device__ float  g_carry[NCHT][DD];                        // chunk carry-in state

// ---------------- PTX helpers (family-independent only) ----------------
__device__ __forceinline__ uint32_t smem_u32(const void* p) {
    uint32_t a;
    asm("{ .reg .u64 t; cvta.to.shared.u64 t, %1; cvt.u32.u64 %0, t; }" : "=r"(a) : "l"(p));
    return a;
}
__device__ __forceinline__ void cp16(uint32_t dst, const void* src) {
    asm volatile("cp.async.cg.shared.global [%0], [%1], 16;" :: "r"(dst), "l"(src) : "memory");
}
__device__ __forceinline__ void cp_commit() {
    asm volatile("cp.async.commit_group;" ::: "memory");
}
template<int N>
__device__ __forceinline__ void cp_wait() {
    asm volatile("cp.async.wait_group %0;" :: "n"(N) : "memory");
}
__device__ __forceinline__ void ldsm4(uint32_t* r, uint32_t addr) {
    asm volatile("ldmatrix.sync.aligned.m8n8.x4.shared.b16 {%0,%1,%2,%3}, [%4];"
        : "=r"(r[0]), "=r"(r[1]), "=r"(r[2]), "=r"(r[3]) : "r"(addr));
}
__device__ __forceinline__ void mma16816(float* c, const uint32_t* a, const uint32_t* b) {
    asm volatile("mma.sync.aligned.m16n8k16.row.col.f32.f16.f16.f32 "
        "{%0,%1,%2,%3}, {%4,%5,%6,%7}, {%8,%9}, {%0,%1,%2,%3};"
        : "+f"(c[0]), "+f"(c[1]), "+f"(c[2]), "+f"(c[3])
        : "r"(a[0]), "r"(a[1]), "r"(a[2]), "r"(a[3]), "r"(b[0]), "r"(b[1]));
}
__device__ __forceinline__ float fast_sigmoid(float x) {
    float t;
    asm("tanh.approx.f32 %0, %1;" : "=f"(t) : "f"(x * 0.5f));
    return fmaf(t, 0.5f, 0.5f);
}

// ---------------- conversion ----------------
__global__ __launch_bounds__(256) void conv_A(const float* __restrict__ seq)
{
    size_t gid = (size_t)blockIdx.x * 256 + threadIdx.x;   // MM*DD/8 threads
    size_t e0 = gid * 8;
    float4 x0 = *(const float4*)(seq + e0);
    float4 x1 = *(const float4*)(seq + e0 + 4);
    float xs[8] = {x0.x, x0.y, x0.z, x0.w, x1.x, x1.y, x1.z, x1.w};
    uint32_t w[8];
    #pragma unroll
    for (int i = 0; i < 8; i++)
        w[i] = (uint32_t)__half_as_ushort(__float2half_rn(xs[i]));
    *(uint4*)(g_A + e0) = make_uint4(w[0]|(w[1]<<16), w[2]|(w[3]<<16),
                                     w[4]|(w[5]<<16), w[6]|(w[7]<<16));
}

// B: interleave rows — g_B row r = 2*d+s <- (s ? Wv : Wd)[d]
__global__ __launch_bounds__(256) void conv_B(const float* __restrict__ Wd,
                                              const float* __restrict__ Wv)
{
    size_t gid = (size_t)blockIdx.x * 256 + threadIdx.x;   // NBR*DD/8 = 262144
    int r  = (int)(gid >> 7);        // 0..2047
    int k0 = ((int)gid & 127) * 8;
    int d  = r >> 1, s = r & 1;
    const float* src = (s ? Wv : Wd) + (size_t)d * DD + k0;
    float4 x0 = *(const float4*)src;
    float4 x1 = *(const float4*)(src + 4);
    float xs[8] = {x0.x, x0.y, x0.z, x0.w, x1.x, x1.y, x1.z, x1.w};
    uint32_t w[8];
    #pragma unroll
    for (int i = 0; i < 8; i++)
        w[i] = (uint32_t)__half_as_ushort(__float2half_rn(xs[i]));
    *(uint4*)(g_B + (size_t)r * DD + k0) =
        make_uint4(w[0]|(w[1]<<16), w[2]|(w[3]<<16), w[4]|(w[5]<<16), w[6]|(w[7]<<16));
}

// ---------------- GEMM + fused gate epilogue + per-wm chunk summary ----------
__global__ void __launch_bounds__(256, 2)
gemm_mma(const float* __restrict__ bias_d, const float* __restrict__ bias_v)
{
    extern __shared__ __align__(1024) char smem[];
    const uint32_t sb = smem_u32(smem);
    const int tid = threadIdx.x;
    const int nt = blockIdx.x, mt = blockIdx.y;
    const int m0 = mt * BM;

    const char* gA = (const char*)(g_A + (size_t)m0 * DD);
    const char* gB = (const char*)(g_B + (size_t)nt * BN * DD);

    // ---- loader: SW128 XOR swizzle; 4 x 16B per thread per buffer ----
    auto load_stage = [&](int s, int c) {
        uint32_t st = sb + s * STAGE_BYTES;
        #pragma unroll
        for (int i = 0; i < 4; i++) {
            int uid = i * 256 + tid;           // 0..1023
            int row = uid >> 3, u = uid & 7;
            uint32_t phys = (uint32_t)(row * 128 + (((u ^ (row & 7)) << 4)));
            size_t gofs = (size_t)row * (DD * 2) + (size_t)c * 128 + (size_t)u * 16;
            cp16(st + BUF_A + phys, gA + gofs);
            cp16(st + BUF_B + phys, gB + gofs);
        }
    };

    // ---- compute mapping: 8 warps in 2(m) x 4(n); warp tile 64x32 ----
    const int lane = tid & 31, wid = tid >> 5;
    const int wm = wid >> 2, wn = wid & 3;

    const int arow  = lane & 15;
    const int ahalf = lane >> 4;
    const int brow  = (lane & 7) | (((lane >> 4) & 1) << 3);
    const int bhalf = (lane >> 3) & 1;
    const int swA   = arow & 7;
    const int swB   = brow & 7;

    uint32_t aRowOff[4], bRowOff[2];
    #pragma unroll
    for (int mf = 0; mf < 4; mf++) aRowOff[mf] = (uint32_t)((wm * 64 + mf * 16 + arow) * 128);
    #pragma unroll
    for (int np = 0; np < 2; np++) bRowOff[np] = (uint32_t)((wn * 32 + np * 16 + brow) * 128);

    float acc[4][4][4] = {};

    load_stage(0, 0); cp_commit();
    load_stage(1, 1); cp_commit();
    load_stage(2, 2); cp_commit();

    #pragma unroll 1
    for (int c = 0; c < NKC; c++) {
        cp_wait<2>();
        __syncthreads();

        const int s = c % S_STAGES;
        const uint32_t st = sb + s * STAGE_BYTES;
        #pragma unroll
        for (int kk = 0; kk < 4; kk++) {
            const uint32_t aun = (uint32_t)(((kk * 2 + ahalf) ^ swA) << 4);
            const uint32_t bun = (uint32_t)(((kk * 2 + bhalf) ^ swB) << 4);
            uint32_t ah[4][4], bh[4][2];
            #pragma unroll
            for (int mf = 0; mf < 4; mf++)
                ldsm4(ah[mf], st + BUF_A + aRowOff[mf] + aun);
            #pragma unroll
            for (int np = 0; np < 2; np++) {
                uint32_t r[4];
                ldsm4(r, st + BUF_B + bRowOff[np] + bun);
                bh[np*2+0][0] = r[0]; bh[np*2+0][1] = r[1];
                bh[np*2+1][0] = r[2]; bh[np*2+1][1] = r[3];
            }
            #pragma unroll
            for (int mf = 0; mf < 4; mf++)
                #pragma unroll
                for (int nf = 0; nf < 4; nf++)
                    mma16816(acc[mf][nf], ah[mf], bh[nf]);
        }
        __syncthreads();
        if (c + 3 < NKC) { load_stage(s, c + 3); }
        cp_commit();
    }

    // ==== fused epilogue ====
    // acc[mf][nf][0,1] = (delta_hat, value_hat) at t-local = mf*16+0*8+j;
    //            [2,3] same at t-local = mf*16+8+j   (j = lane>>2)
    // d = nt*64 + wn*16 + nf*4 + (lane&3)
    const int dbase = nt * 64 + wn * 16 + (lane & 3);
    const int j = lane >> 2;
    // warp-native g_ab base (u32 units): warp block is 1024 u32
    uint32_t* __restrict__ wab =
        g_ab + ((((size_t)(mt * 16 + nt) * 2 + wm) * 4 + wn) * 1024) + lane;

    #pragma unroll
    for (int nf = 0; nf < 4; nf++) {
        const int dg = dbase + nf * 4;
        const float bd = bias_d[dg];
        const float bv = bias_v[dg];

        float Ca = 1.0f, Cb = 0.0f;          // running chunk (64 t) composition
        #pragma unroll
        for (int mf = 0; mf < 4; mf++) {
            #pragma unroll
            for (int p = 0; p < 2; p++) {    // (mf,p) ascending == t ascending
                float dh = acc[mf][nf][p*2+0] + bd;
                float vh = acc[mf][nf][p*2+1] + bv;
                float del = fast_sigmoid(dh);
                float a = 1.0f - del;
                float b = del * vh;
                __half2 h = __floats2half2_rn(a, b);
                wab[(((nf * 4 + mf) * 2 + p) << 5)] = *(uint32_t*)&h;  // coalesced
                // ordered butterfly over j (lane bits 2..4): product of 8 t's
                float Wa = a, Wb = b;
                #pragma unroll
                for (int mk = 4; mk <= 16; mk <<= 1) {
                    float oa = __shfl_xor_sync(0xffffffffu, Wa, mk);
                    float ob = __shfl_xor_sync(0xffffffffu, Wb, mk);
                    if (lane & mk) {         // self upper: self ∘ other
                        Wb = fmaf(Wa, ob, Wb);
                        Wa = Wa * oa;
                    } else {                 // other upper: other ∘ self
                        Wb = fmaf(oa, Wb, ob);
                        Wa = oa * Wa;
                    }
                }
                // compose into running chunk map: C = W ∘ C
                Cb = fmaf(Wa, Cb, Wb);
                Ca = Wa * Ca;
            }
        }
        if (j == 0)                          // lanes 0..3 publish dd 0..3
            g_AS[mt * 2 + wm][dg] = make_float2(Ca, Cb);
    }
}

// ---------------- scan phase 2: carry-in per 64-t chunk ----------------
__global__ __launch_bounds__(256) void scan_phase2()
{
    const int g = blockIdx.x * 256 + threadIdx.x;   // 2048 threads
    const int b = g >> 8;
    const int d0 = (g & 255) * 4;
    float4 cur = make_float4(0.f, 0.f, 0.f, 0.f);
    #pragma unroll 1
    for (int grp = 0; grp < 8; grp++) {
        float4 x[8], y[8];
        #pragma unroll
        for (int k = 0; k < 8; k++) {
            const float4* asp = (const float4*)&g_AS[b * NCHB + grp * 8 + k][d0];
            x[k] = asp[0];   // (a0,s0,a1,s1)
            y[k] = asp[1];   // (a2,s2,a3,s3)
        }
        #pragma unroll
        for (int k = 0; k < 8; k++) {
            *(float4*)&g_carry[b * NCHB + grp * 8 + k][d0] = cur;
            cur.x = fmaf(x[k].x, cur.x, x[k].y);
            cur.y = fmaf(x[k].z, cur.y, x[k].w);
            cur.z = fmaf(y[k].x, cur.z, y[k].y);
            cur.w = fmaf(y[k].z, cur.w, y[k].w);
        }
    }
}

// ---------------- scan phase 3: replay 64-t chunk, emit fp32 [t][d] --------
__global__ __launch_bounds__(256) void scan_phase3(float* __restrict__ out)
{
    const int x = blockIdx.x;          // chunk within batch: 0..63
    const int b = blockIdx.y;
    const int mt = b * 32 + (x >> 1), wm = x & 1;
    const int ch = b * NCHB + x;       // == mt*2+wm
    const int tid = threadIdx.x;       // = nt*16 + wn*4 + nf  -> d = tid*4
    const int ntp = tid >> 4, wnp = (tid >> 2) & 3, nfp = tid & 3;

    const uint32_t* __restrict__ tb =
        g_ab + (((((size_t)(mt * 16 + ntp) * 2 + wm) * 4 + wnp) * 4 + nfp) * 256);
    float4 cur = *(const float4*)&g_carry[ch][tid * 4];
    const size_t obase = ((size_t)mt * BM + (size_t)wm * 64) * DD + tid * 4;

    #pragma unroll
    for (int mf = 0; mf < 4; mf++) {
        #pragma unroll
        for (int p = 0; p < 2; p++) {
            const uint32_t* seg = tb + (mf * 2 + p) * 32;
            #pragma unroll
            for (int jj = 0; jj < 8; jj++) {
                uint4 u = *(const uint4*)(seg + jj * 4);
                float2 p0 = __half22float2(*(__half2*)&u.x);
                float2 p1 = __half22float2(*(__half2*)&u.y);
                float2 p2 = __half22float2(*(__half2*)&u.z);
                float2 p3 = __half22float2(*(__half2*)&u.w);
                cur.x = fmaf(p0.x, cur.x, p0.y);
                cur.y = fmaf(p1.x, cur.y, p1.y);
                cur.z = fmaf(p2.x, cur.z, p2.y);
                cur.w = fmaf(p3.x, cur.w, p3.y);
                const int tl = mf * 16 + p * 8 + jj;
                *(float4*)(out + obase + (size_t)tl * DD) = cur;
            }
        }
    }
}

// ---------------- launch ----------------
extern "C" void kernel_launch(void* const* d_in, const int* in_sizes, int n_in,
                              void* d_out, int out_size)
{
    const float* seq = (const float*)d_in[0];
    const float* Wd  = (const float*)d_in[1];
    const float* bd  = (const float*)d_in[2];
    const float* Wv  = (const float*)d_in[3];
    const float* bv  = (const float*)d_in[4];
    float* out = (float*)d_out;

    cudaFuncSetAttribute(gemm_mma, cudaFuncAttributeMaxDynamicSharedMemorySize, SMEM_TOTAL);

    conv_A<<<16384, 256>>>(seq);
    conv_B<<<1024, 256>>>(Wd, Wv);
    gemm_mma<<<dim3(NT, MT), 256, SMEM_TOTAL>>>(bd, bv);

    scan_phase2<<<8, 256>>>();
    scan_phase3<<<dim3(NCHB, BB), 256>>>(out);
}